// round 16
// baseline (speedup 1.0000x reference)
#include <cuda_runtime.h>
#include <cuda_fp16.h>
#include <cstdint>

// ---------------------------------------------------------------------------
// Problem constants
// ---------------------------------------------------------------------------
#define KDIM 256
#define NDIM 256
#define KC   64
#define NCHUNK 4
#define NTHR 512                    // 8 consumer warps + 8 producer warps
#define BM 64

// SMEM layout (bytes)
#define OFF_STAB 0                  // 8 x float4 = 128B
#define OFF_CTAB 128                // padded (c0,c1) pairs, 2432B
#define OFF_A    3072               // 4 buffers (one per chunk)
#define A_BUF    8192               // 64 rows x 128B
#define OFF_B    (OFF_A + 4 * A_BUF)        // 35840
#define B_CHUNK  32768              // 256 rows x 128B
#define SMEM_TOTAL (OFF_B + 4 * B_CHUNK)    // 166912

#define MAGIC   12582912.0f         /* 1.5 * 2^23 */
#define MAGIC_I 0x4B400000

// ---------------------------------------------------------------------------
// Prologue output: fp16 pre-swizzled B images
// ---------------------------------------------------------------------------
__device__ __align__(16) unsigned char g_Bf[NCHUNK][NDIM * 128];

// ---------------------------------------------------------------------------
// helpers
// ---------------------------------------------------------------------------
__device__ __forceinline__ uint32_t smem_u32(const void* p) {
    uint32_t a;
    asm("{ .reg .u64 t; cvta.to.shared.u64 t, %1; cvt.u32.u64 %0, t; }" : "=r"(a) : "l"(p));
    return a;
}

__device__ __forceinline__ void ldsm_x4(uint32_t& r0, uint32_t& r1, uint32_t& r2,
                                        uint32_t& r3, uint32_t addr) {
    asm volatile("ldmatrix.sync.aligned.m8n8.x4.shared.b16 {%0,%1,%2,%3}, [%4];"
                 : "=r"(r0), "=r"(r1), "=r"(r2), "=r"(r3) : "r"(addr));
}

__device__ __forceinline__ void mma_fp16(float* c, const uint32_t* a,
                                         uint32_t b0, uint32_t b1) {
    asm volatile(
        "mma.sync.aligned.m16n8k16.row.col.f32.f16.f16.f32 "
        "{%0,%1,%2,%3}, {%4,%5,%6,%7}, {%8,%9}, {%0,%1,%2,%3};"
        : "+f"(c[0]), "+f"(c[1]), "+f"(c[2]), "+f"(c[3])
        : "r"(a[0]), "r"(a[1]), "r"(a[2]), "r"(a[3]), "r"(b0), "r"(b1));
}

#define CP_ASYNC16(saddr, gptr) \
    asm volatile("cp.async.cg.shared.global [%0], [%1], 16;" :: "r"(saddr), "l"(gptr))
#define CP_COMMIT() asm volatile("cp.async.commit_group;")
#define CP_WAITN(n) asm volatile("cp.async.wait_group %0;" :: "n"(n))

#define BAR_SYNC(id)   asm volatile("bar.sync %0, %1;"   :: "r"(id), "n"(NTHR) : "memory")
#define BAR_ARRIVE(id) asm volatile("bar.arrive %0, %1;" :: "r"(id), "n"(NTHR) : "memory")
#define MEMBAR_CTA()   asm volatile("membar.cta;" ::: "memory")

__device__ __forceinline__ uint32_t pack_h2(float a0, float a1) {
    __half2 h = __floats2half2_rn(a0, a1);
    return *reinterpret_cast<uint32_t*>(&h);
}

__device__ __host__ __forceinline__ int ctab_off(int k) {
    return k * 8 + (k >> 4) * 16;
}

// ---------------------------------------------------------------------------
// Prologue: fp16 pre-swizzled B images (validated R15 logic)
// ---------------------------------------------------------------------------
__global__ void kan_prologue(const float* __restrict__ oc) {
    int gid = blockIdx.x * 256 + threadIdx.x;   // 0..8191
    int n   = gid >> 5;                          // B row 0..255
    int g   = gid & 31;                          // k-granule (8 fp32)
    int chunk = g >> 3;
    int colg  = g & 7;
    const float4* src = (const float4*)(oc + n * KDIM + g * 8);
    float4 v0 = src[0], v1 = src[1];
    float a[8] = {v0.x, v0.y, v0.z, v0.w, v1.x, v1.y, v1.z, v1.w};
    uint32_t h[4];
#pragma unroll
    for (int e = 0; e < 4; e++) h[e] = pack_h2(a[2 * e], a[2 * e + 1]);
    int off = n * 128 + ((colg ^ (n & 7)) << 4);
    *(uint4*)(g_Bf[chunk] + off) = make_uint4(h[0], h[1], h[2], h[3]);
}

// ---------------------------------------------------------------------------
// Activation (validated R15): v = 7 - 7/(e^{2x}+1); magic floor; seg cubics
// ---------------------------------------------------------------------------
__device__ __forceinline__ float kan_act2(float xv, float c0, float c1,
                                          const float4* __restrict__ stab) {
    float e2 = __expf(2.0f * xv);
    float v  = 7.0f - __fdividef(7.0f, e2 + 1.0f);
    float wf = __fadd_rz(v, MAGIC);
    int   j  = __float_as_int(wf) - MAGIC_I;
    j = j > 6 ? 6 : j;
    float u  = v - (wf - MAGIC);
    float4 sB = stab[j];
    float4 sA = stab[j + 1];
    float b30 = fmaf(fmaf(fmaf(sA.w, u, sA.z), u, sA.y), u, sA.x);
    float b31 = fmaf(fmaf(fmaf(sB.w, u, sB.z), u, sB.y), u, sB.x);
    return fmaf(c0, b30, c1 * b31);
}

__device__ __forceinline__ void act16(const float* av, int kb, const char* ctab,
                                      const float4* __restrict__ stab, float* r) {
#pragma unroll
    for (int p = 0; p < 8; p++) {
        int k0 = kb + 2 * p;
        float4 cg = *(const float4*)(ctab + ctab_off(k0));
        r[2 * p]     = kan_act2(av[2 * p],     cg.x, cg.y, stab);
        r[2 * p + 1] = kan_act2(av[2 * p + 1], cg.z, cg.w, stab);
    }
}

// ---------------------------------------------------------------------------
// Main: warp-specialized fused kernel.
// Warps 0-7: HMMA consumers (BM=64 x N=256).  Warps 8-15: act producers.
// A: 4 buffers (1/chunk, no reuse). B: resident, 4 cp.async groups.
// Sync: named barriers 1..4 (arrive by producers, sync by consumers).
// ---------------------------------------------------------------------------
__global__ void __launch_bounds__(NTHR, 1)
kan_main(const float* __restrict__ x, const float* __restrict__ ic,
         float* __restrict__ out) {
    extern __shared__ __align__(1024) char smem[];
    const uint32_t sbase = smem_u32(smem);
    const int tid = threadIdx.x;
    const int lid = tid & 31;
    const int m0  = blockIdx.x * BM;

    if (tid >= 256) {
        // -------- producer setup: tables + B cp.async (4 groups) --------
        const int ptid = tid - 256;
        if (ptid < 8) {
            const float P[4][4] = {
                {0.f, 0.f, 0.f,  1.f},
                {1.f, 3.f, 3.f, -3.f},
                {4.f, 0.f, -6.f, 3.f},
                {1.f, -3.f, 3.f, -1.f}
            };
            float4 s = make_float4(0.f, 0.f, 0.f, 0.f);
            if (ptid >= 1 && ptid <= 4) {
                const float s6 = 1.0f / 6.0f;
                int m = ptid - 1;
                s = make_float4(P[m][0] * s6, P[m][1] * s6, P[m][2] * s6, P[m][3] * s6);
            }
            ((float4*)(smem + OFF_STAB))[ptid] = s;
        }
        if (ptid < 128) {
            int q = ptid;
            float c0a = __ldg(&ic[10 * q + 0]);
            float c1a = __ldg(&ic[10 * q + 1]);
            float c0b = __ldg(&ic[10 * q + 5]);
            float c1b = __ldg(&ic[10 * q + 6]);
            *(float4*)(smem + OFF_CTAB + 16 * q + 16 * (q >> 3)) =
                make_float4(c0a, c1a, c0b, c1b);
        }
#pragma unroll
        for (int c = 0; c < NCHUNK; c++) {
#pragma unroll
            for (int i = 0; i < 8; i++) {
                int idx = ptid + i * 256;            // 0..2047 granules
                CP_ASYNC16(sbase + OFF_B + c * B_CHUNK + idx * 16,
                           (const char*)g_Bf[c] + idx * 16);
            }
            CP_COMMIT();
        }
    }
    __syncthreads();                 // tables visible; roles diverge after this

    if (tid < 256) {
        // ======================= CONSUMERS (8 warps) =======================
        const int wid = tid >> 5;
        const int wm  = (wid >> 2) * 32;
        const int wn  = (wid & 3) * 64;
        const int lr   = lid & 15;
        const int lhal = lid >> 4;

        float acc[2][8][4];
#pragma unroll
        for (int mt = 0; mt < 2; mt++)
#pragma unroll
            for (int nt = 0; nt < 8; nt++)
#pragma unroll
                for (int e = 0; e < 4; e++) acc[mt][nt][e] = 0.0f;

#pragma unroll
        for (int c = 0; c < NCHUNK; c++) {
            BAR_SYNC(1 + c);                         // A(c)+B(c) ready
            const uint32_t aBase = sbase + OFF_A + c * A_BUF;
            const uint32_t bBase = sbase + OFF_B + c * B_CHUNK;
#pragma unroll
            for (int ks = 0; ks < 4; ks++) {
                const int g = ks * 2 + lhal;
                uint32_t a[2][4];
#pragma unroll
                for (int mt = 0; mt < 2; mt++) {
                    int r = wm + mt * 16 + lr;
                    uint32_t off = (uint32_t)(r * 128 + ((g ^ (r & 7)) << 4));
                    ldsm_x4(a[mt][0], a[mt][1], a[mt][2], a[mt][3], aBase + off);
                }
#pragma unroll
                for (int np = 0; np < 4; np++) {
                    int r = wn + np * 16 + lr;
                    uint32_t off = (uint32_t)(r * 128 + ((g ^ (r & 7)) << 4));
                    uint32_t b[4];
                    ldsm_x4(b[0], b[1], b[2], b[3], bBase + off);
#pragma unroll
                    for (int mt = 0; mt < 2; mt++) {
                        mma_fp16(acc[mt][2 * np + 0], a[mt], b[0], b[2]);
                        mma_fp16(acc[mt][2 * np + 1], a[mt], b[1], b[3]);
                    }
                }
            }
        }

        // epilogue: direct fp32 stores
        const int rq = lid >> 2;
        const int cq = (lid & 3) * 2;
#pragma unroll
        for (int mt = 0; mt < 2; mt++) {
            int row = m0 + wm + mt * 16 + rq;
#pragma unroll
            for (int nt = 0; nt < 8; nt++) {
                int col = wn + nt * 8 + cq;
                float2 v0 = make_float2(acc[mt][nt][0], acc[mt][nt][1]);
                float2 v1 = make_float2(acc[mt][nt][2], acc[mt][nt][3]);
                *(float2*)(out + (size_t)row * NDIM + col)       = v0;
                *(float2*)(out + (size_t)(row + 8) * NDIM + col) = v1;
            }
        }
    } else {
        // ======================= PRODUCERS (8 warps) =======================
        const int ptid = tid - 256;
        const int arow = ptid >> 2;          // 0..63
        const int aq   = ptid & 3;           // k-quarter (16 elems)
        const int swg0 = ((aq * 2)     ^ (arow & 7)) << 4;
        const int swg1 = ((aq * 2 + 1) ^ (arow & 7)) << 4;
        const float4* stab = (const float4*)(smem + OFF_STAB);
        const char*   ctab = smem + OFF_CTAB;
        const float4* xbase = (const float4*)(x + (size_t)(m0 + arow) * KDIM + aq * 16);

        float4 xv0 = xbase[0], xv1 = xbase[1], xv2 = xbase[2], xv3 = xbase[3];

#pragma unroll
        for (int c = 0; c < NCHUNK; c++) {
            float av[16] = {xv0.x, xv0.y, xv0.z, xv0.w, xv1.x, xv1.y, xv1.z, xv1.w,
                            xv2.x, xv2.y, xv2.z, xv2.w, xv3.x, xv3.y, xv3.z, xv3.w};
            float r[16];
            act16(av, c * KC + aq * 16, ctab, stab, r);
            char* ad = smem + OFF_A + c * A_BUF + arow * 128;
            *(uint4*)(ad + swg0) = make_uint4(pack_h2(r[0], r[1]),  pack_h2(r[2], r[3]),
                                              pack_h2(r[4], r[5]),  pack_h2(r[6], r[7]));
            *(uint4*)(ad + swg1) = make_uint4(pack_h2(r[8], r[9]),  pack_h2(r[10], r[11]),
                                              pack_h2(r[12], r[13]), pack_h2(r[14], r[15]));

            // B(c) landed?  (groups complete in commit order)
            if (c == 0)      CP_WAITN(3);
            else if (c == 1) CP_WAITN(2);
            else if (c == 2) CP_WAITN(1);
            else             CP_WAITN(0);

            MEMBAR_CTA();                    // STS + cp.async visible to CTA
            BAR_ARRIVE(1 + c);               // release A(c)+B(c) to consumers

            if (c < NCHUNK - 1) {
                const float4* xp = xbase + (c + 1) * (KC / 4);
                xv0 = xp[0]; xv1 = xp[1]; xv2 = xp[2]; xv3 = xp[3];
            }
        }
    }
}

// ---------------------------------------------------------------------------
extern "C" void kernel_launch(void* const* d_in, const int* in_sizes, int n_in,
                              void* d_out, int out_size) {
    const float* x  = (const float*)d_in[0];   // [B,S,256] fp32
    const float* ic = (const float*)d_in[1];   // [256,5]   fp32
    const float* oc = (const float*)d_in[2];   // [256,256] fp32
    float* out = (float*)d_out;

    const int M = in_sizes[0] / KDIM;          // 65536

    cudaFuncSetAttribute(kan_main, cudaFuncAttributeMaxDynamicSharedMemorySize, SMEM_TOTAL);

    kan_prologue<<<32, 256>>>(oc);
    kan_main<<<M / BM, NTHR, SMEM_TOTAL>>>(x, ic, out);
}

// round 17
// speedup vs baseline: 1.0559x; 1.0559x over previous
#include <cuda_runtime.h>
#include <cuda_fp16.h>
#include <cstdint>

// ---------------------------------------------------------------------------
// Problem constants
// ---------------------------------------------------------------------------
#define KDIM 256
#define NDIM 256
#define KC   64
#define NCHUNK (KDIM / KC)
#define M_MAX 65536
#define BM 64                       // gemm CTA M tile

#define MAGIC   12582912.0f         /* 1.5 * 2^23 */
#define MAGIC_I 0x4B400000

// ---------------------------------------------------------------------------
// Device buffers
// ---------------------------------------------------------------------------
__device__ __align__(16) __half g_inner[M_MAX * KDIM];            // 32MB
__device__ __align__(16) unsigned char g_Bf[NCHUNK][NDIM * 128];  // swizzled B

// ---------------------------------------------------------------------------
// helpers
// ---------------------------------------------------------------------------
__device__ __forceinline__ uint32_t smem_u32(const void* p) {
    uint32_t a;
    asm("{ .reg .u64 t; cvta.to.shared.u64 t, %1; cvt.u32.u64 %0, t; }" : "=r"(a) : "l"(p));
    return a;
}

__device__ __forceinline__ void ldsm_x4(uint32_t& r0, uint32_t& r1, uint32_t& r2,
                                        uint32_t& r3, uint32_t addr) {
    asm volatile("ldmatrix.sync.aligned.m8n8.x4.shared.b16 {%0,%1,%2,%3}, [%4];"
                 : "=r"(r0), "=r"(r1), "=r"(r2), "=r"(r3) : "r"(addr));
}

__device__ __forceinline__ void mma_fp16(float* c, const uint32_t* a,
                                         uint32_t b0, uint32_t b1) {
    asm volatile(
        "mma.sync.aligned.m16n8k16.row.col.f32.f16.f16.f32 "
        "{%0,%1,%2,%3}, {%4,%5,%6,%7}, {%8,%9}, {%0,%1,%2,%3};"
        : "+f"(c[0]), "+f"(c[1]), "+f"(c[2]), "+f"(c[3])
        : "r"(a[0]), "r"(a[1]), "r"(a[2]), "r"(a[3]), "r"(b0), "r"(b1));
}

#define CP_ASYNC16(saddr, gptr) \
    asm volatile("cp.async.cg.shared.global [%0], [%1], 16;" :: "r"(saddr), "l"(gptr))
#define CP_COMMIT() asm volatile("cp.async.commit_group;")
#define CP_WAIT0()  asm volatile("cp.async.wait_group 0;")

__device__ __forceinline__ uint32_t pack_h2(float a0, float a1) {
    __half2 h = __floats2half2_rn(a0, a1);
    return *reinterpret_cast<uint32_t*>(&h);
}

__device__ __host__ __forceinline__ int ctab_off(int k) {
    return k * 8 + (k >> 4) * 16;
}

// ---------------------------------------------------------------------------
// Activation (validated): v = 7 - 7/(e^{2x}+1); magic floor; segment cubics
// ---------------------------------------------------------------------------
__device__ __forceinline__ float kan_act2(float xv, float c0, float c1,
                                          const float4* __restrict__ stab) {
    float e2 = __expf(2.0f * xv);
    float v  = 7.0f - __fdividef(7.0f, e2 + 1.0f);
    float wf = __fadd_rz(v, MAGIC);
    int   j  = __float_as_int(wf) - MAGIC_I;
    j = j > 6 ? 6 : j;
    float u  = v - (wf - MAGIC);
    float4 sB = stab[j];        // B31 segment cubic
    float4 sA = stab[j + 1];    // B30 segment cubic
    float b30 = fmaf(fmaf(fmaf(sA.w, u, sA.z), u, sA.y), u, sA.x);
    float b31 = fmaf(fmaf(fmaf(sB.w, u, sB.z), u, sB.y), u, sB.x);
    return fmaf(c0, b30, c1 * b31);
}

// ---------------------------------------------------------------------------
// Kernel 1: activation, fully coalesced. One thread = 4 consecutive elements
// (one float4 load, one uint2 fp16 store). Blocks 0..31 also build g_Bf.
// ---------------------------------------------------------------------------
__global__ void __launch_bounds__(256)
kan_act_kernel(const float* __restrict__ x, const float* __restrict__ ic,
               const float* __restrict__ oc) {
    __shared__ __align__(16) float4 s_stab[8];
    __shared__ __align__(16) char s_ctab[2432];
    const int tid = threadIdx.x;

    // build stab (bit-identical arithmetic)
    if (tid < 8) {
        const float P[4][4] = {
            {0.f, 0.f, 0.f,  1.f},
            {1.f, 3.f, 3.f, -3.f},
            {4.f, 0.f, -6.f, 3.f},
            {1.f, -3.f, 3.f, -1.f}
        };
        float4 s = make_float4(0.f, 0.f, 0.f, 0.f);
        if (tid >= 1 && tid <= 4) {
            const float s6 = 1.0f / 6.0f;
            int m = tid - 1;
            s = make_float4(P[m][0] * s6, P[m][1] * s6, P[m][2] * s6, P[m][3] * s6);
        }
        s_stab[tid] = s;
    }
    // build ctab straight from ic
    if (tid < 128) {
        int q = tid;                         // granule: channels 2q, 2q+1
        float c0a = __ldg(&ic[10 * q + 0]);
        float c1a = __ldg(&ic[10 * q + 1]);
        float c0b = __ldg(&ic[10 * q + 5]);
        float c1b = __ldg(&ic[10 * q + 6]);
        *(float4*)(s_ctab + 16 * q + 16 * (q >> 3)) = make_float4(c0a, c1a, c0b, c1b);
    }
    __syncthreads();
    const float4* stab = s_stab;

    // ---- act: 4 elements per thread, coalesced ----
    const size_t g = (size_t)blockIdx.x * 256 + tid;   // float4 index
    const int t = (int)(g & 63);                        // k-granule of 4: k0 = 4t

    float4 xv = *(const float4*)(x + 4 * g);
    float4 cg0 = *(const float4*)(s_ctab + ctab_off(4 * t));       // ch 4t,4t+1
    float4 cg1 = *(const float4*)(s_ctab + ctab_off(4 * t + 2));   // ch 4t+2,4t+3

    float r0 = kan_act2(xv.x, cg0.x, cg0.y, stab);
    float r1 = kan_act2(xv.y, cg0.z, cg0.w, stab);
    float r2 = kan_act2(xv.z, cg1.x, cg1.y, stab);
    float r3 = kan_act2(xv.w, cg1.z, cg1.w, stab);

    *(uint2*)(g_inner + 4 * g) = make_uint2(pack_h2(r0, r1), pack_h2(r2, r3));

    // ---- blocks 0..31: build pre-swizzled fp16 B images ----
    if (blockIdx.x < 32) {
        int bgid = blockIdx.x * 256 + tid;          // 0..8191
        int n    = bgid >> 5;                        // B row 0..255
        int gg   = bgid & 31;                        // k-granule (8 fp32)
        int chunk = gg >> 3;
        int colg  = gg & 7;
        const float4* src = (const float4*)(oc + n * KDIM + gg * 8);
        float4 v0 = src[0], v1 = src[1];
        float a[8] = {v0.x, v0.y, v0.z, v0.w, v1.x, v1.y, v1.z, v1.w};
        uint32_t h[4];
#pragma unroll
        for (int e = 0; e < 4; e++) h[e] = pack_h2(a[2 * e], a[2 * e + 1]);
        int off = n * 128 + ((colg ^ (n & 7)) << 4);
        *(uint4*)(g_Bf[chunk] + off) = make_uint4(h[0], h[1], h[2], h[3]);
    }
}

// ---------------------------------------------------------------------------
// Kernel 2: pure fp16 HMMA GEMM (byte-identical to R15's 32.1us version)
// ---------------------------------------------------------------------------
#define ST_A(s) ((s) * 40960)
#define ST_B(s) ((s) * 40960 + 8192)
#define K2_SMEM (2 * 40960)          // 81920 -> 2 CTAs/SM

__global__ void __launch_bounds__(256, 2)
kan_gemm(float* __restrict__ out) {
    extern __shared__ __align__(1024) char smem[];
    const uint32_t sbase = smem_u32(smem);
    const int tid = threadIdx.x;
    const int wid = tid >> 5;
    const int lid = tid & 31;
    const int m0  = blockIdx.x * BM;

    const int wm = (wid >> 2) * 32;      // 2 M-warps
    const int wn = (wid & 3) * 64;       // 4 N-warps

    const char* innerBase = (const char*)(g_inner + (size_t)m0 * KDIM);

    auto issue = [&](int c, int s) {
#pragma unroll
        for (int i = 0; i < 2; i++) {                 // A: 512 granules
            int idx = tid + i * 256;
            int r = idx >> 3, g = idx & 7;
            const char* src = innerBase + (size_t)r * 512 + c * 128 + g * 16;
            uint32_t dst = sbase + ST_A(s) + r * 128 + ((g ^ (r & 7)) << 4);
            CP_ASYNC16(dst, src);
        }
        const char* bsrc = (const char*)g_Bf[c];
#pragma unroll
        for (int i = 0; i < 8; i++) {                 // B: 2048 granules
            int idx = tid + i * 256;
            CP_ASYNC16(sbase + ST_B(s) + idx * 16, bsrc + idx * 16);
        }
        CP_COMMIT();
    };

    issue(0, 0);

    float acc[2][8][4];
#pragma unroll
    for (int mt = 0; mt < 2; mt++)
#pragma unroll
        for (int nt = 0; nt < 8; nt++)
#pragma unroll
            for (int e = 0; e < 4; e++) acc[mt][nt][e] = 0.0f;

    const int lr   = lid & 15;
    const int lhal = lid >> 4;

#pragma unroll
    for (int c = 0; c < NCHUNK; c++) {
        const int s = c & 1;
        CP_WAIT0();
        __syncthreads();

        if (c < NCHUNK - 1) issue(c + 1, s ^ 1);

        const uint32_t aBase = sbase + ST_A(s);
        const uint32_t bBase = sbase + ST_B(s);
#pragma unroll
        for (int ks = 0; ks < 4; ks++) {
            const int g = ks * 2 + lhal;
            uint32_t a[2][4];
#pragma unroll
            for (int mt = 0; mt < 2; mt++) {
                int r = wm + mt * 16 + lr;
                uint32_t off = (uint32_t)(r * 128 + ((g ^ (r & 7)) << 4));
                ldsm_x4(a[mt][0], a[mt][1], a[mt][2], a[mt][3], aBase + off);
            }
#pragma unroll
            for (int np = 0; np < 4; np++) {
                int r = wn + np * 16 + lr;
                uint32_t off = (uint32_t)(r * 128 + ((g ^ (r & 7)) << 4));
                uint32_t b[4];
                ldsm_x4(b[0], b[1], b[2], b[3], bBase + off);
#pragma unroll
                for (int mt = 0; mt < 2; mt++) {
                    mma_fp16(acc[mt][2 * np + 0], a[mt], b[0], b[2]);
                    mma_fp16(acc[mt][2 * np + 1], a[mt], b[1], b[3]);
                }
            }
        }
    }

    // epilogue
    {
        const int rq = lid >> 2;
        const int cq = (lid & 3) * 2;
#pragma unroll
        for (int mt = 0; mt < 2; mt++) {
            int row = m0 + wm + mt * 16 + rq;
#pragma unroll
            for (int nt = 0; nt < 8; nt++) {
                int col = wn + nt * 8 + cq;
                float2 v0 = make_float2(acc[mt][nt][0], acc[mt][nt][1]);
                float2 v1 = make_float2(acc[mt][nt][2], acc[mt][nt][3]);
                *(float2*)(out + (size_t)row * NDIM + col)       = v0;
                *(float2*)(out + (size_t)(row + 8) * NDIM + col) = v1;
            }
        }
    }
}

// ---------------------------------------------------------------------------
extern "C" void kernel_launch(void* const* d_in, const int* in_sizes, int n_in,
                              void* d_out, int out_size) {
    const float* x  = (const float*)d_in[0];   // [B,S,256] fp32
    const float* ic = (const float*)d_in[1];   // [256,5]   fp32
    const float* oc = (const float*)d_in[2];   // [256,256] fp32
    float* out = (float*)d_out;

    const int M = in_sizes[0] / KDIM;          // 65536

    cudaFuncSetAttribute(kan_gemm, cudaFuncAttributeMaxDynamicSharedMemorySize, K2_SMEM);

    kan_act_kernel<<<(M * KDIM) / (4 * 256), 256>>>(x, ic, oc);  // 16384 blocks
    kan_gemm<<<M / BM, 256, K2_SMEM>>>(out);
}